// round 9
// baseline (speedup 1.0000x reference)
#include <cuda_runtime.h>
#include <cuda_fp16.h>
#include <cstdint>

#define B_     4
#define T_     2048
#define H_     16
#define D_     64
#define INNER_ 1024
#define DM_    1024
#define KPROJ  512

// ---------------- device scratch (no allocation) ----------------
__device__ __half    g_xh [(size_t)B_*T_*DM_];          // x in fp16
__device__ uint32_t  g_wq [(KPROJ/2)*INNER_];           // weights, k-pair packed words
__device__ uint32_t  g_wk [(KPROJ/2)*INNER_];
__device__ uint32_t  g_wv [(KPROJ/2)*INNER_];
__device__ uint32_t  g_wo [(INNER_/2)*DM_];
__device__ __half    g_q  [(size_t)B_*H_*T_*D_];        // pre-scaled by (1/8)*log2e
__device__ __half    g_k  [(size_t)B_*H_*T_*D_];
__device__ __half    g_v  [(size_t)B_*H_*T_*D_];
__device__ uint32_t  g_vp [(size_t)B_*H_*(T_/2)*D_];    // V key-pair packed words
__device__ __half    g_aoh[(size_t)B_*T_*INNER_];       // attn out, [b][t][h*64+d]

#define SCALE_LOG2E 0.18033688011112042f   // (1/8) * log2(e)

// ---------------- helpers ----------------
__device__ __forceinline__ uint32_t f22h2(float lo, float hi) {
    __half2 h = __floats2half2_rn(lo, hi);
    return *reinterpret_cast<uint32_t*>(&h);
}
__device__ __forceinline__ float ex2f(float x) {
    float r; asm("ex2.approx.f32 %0, %1;" : "=f"(r) : "f"(x)); return r;
}
__device__ __forceinline__ void mma16(float& c0, float& c1, float& c2, float& c3,
                                      uint32_t a0, uint32_t a1, uint32_t a2, uint32_t a3,
                                      uint32_t b0, uint32_t b1) {
    asm volatile(
        "mma.sync.aligned.m16n8k16.row.col.f32.f16.f16.f32 "
        "{%0,%1,%2,%3},{%4,%5,%6,%7},{%8,%9},{%0,%1,%2,%3};"
        : "+f"(c0), "+f"(c1), "+f"(c2), "+f"(c3)
        : "r"(a0), "r"(a1), "r"(a2), "r"(a3), "r"(b0), "r"(b1));
}
__device__ __forceinline__ void cpa16(void* dst, const void* src) {
    uint32_t d = (uint32_t)__cvta_generic_to_shared(dst);
    asm volatile("cp.async.cg.shared.global [%0], [%1], 16;" :: "r"(d), "l"(src));
}
#define CP_COMMIT asm volatile("cp.async.commit_group;")
#define CP_WAIT2  asm volatile("cp.async.wait_group 2;")
#define CP_WAIT1  asm volatile("cp.async.wait_group 1;")
#define CP_WAIT0  asm volatile("cp.async.wait_group 0;")

// ---------------- prep: x->fp16 + all 4 weights (one launch) ----------------
__device__ __forceinline__ void cvtw_body(const float* __restrict__ W,
                                          uint32_t* __restrict__ base, int lb) {
    int idx = lb * 256 + threadIdx.x;
    int kp = idx >> 8, c4 = idx & 255;
    float4 r0 = *(const float4*)(W + (size_t)(2 * kp)     * INNER_ + c4 * 4);
    float4 r1 = *(const float4*)(W + (size_t)(2 * kp + 1) * INNER_ + c4 * 4);
    *(uint4*)(base + (size_t)kp * INNER_ + c4 * 4) =
        make_uint4(f22h2(r0.x, r1.x), f22h2(r0.y, r1.y),
                   f22h2(r0.z, r1.z), f22h2(r0.w, r1.w));
}

__global__ __launch_bounds__(256) void prep_all(const float* __restrict__ x,
                                                const float* __restrict__ Wq,
                                                const float* __restrict__ Wk,
                                                const float* __restrict__ Wv,
                                                const float* __restrict__ Wo) {
    int blk = blockIdx.x;
    if (blk < 4096) {                       // x -> fp16, 8 floats/thread
        size_t i = ((size_t)blk * 256 + threadIdx.x) * 8;
        float4 a = *(const float4*)(x + i);
        float4 b = *(const float4*)(x + i + 4);
        *(uint4*)((uint32_t*)g_xh + i / 2) =
            make_uint4(f22h2(a.x, a.y), f22h2(a.z, a.w),
                       f22h2(b.x, b.y), f22h2(b.z, b.w));
    } else if (blk < 4352) cvtw_body(Wq, g_wq, blk - 4096);
    else if (blk < 4608)   cvtw_body(Wk, g_wk, blk - 4352);
    else if (blk < 4864)   cvtw_body(Wv, g_wv, blk - 4608);
    else                   cvtw_body(Wo, g_wo, blk - 4864);
}

// ---------------- prep: pack V into key-pair words ----------------
__global__ __launch_bounds__(256) void pack_v() {
    int idx = blockIdx.x * 256 + threadIdx.x;
    int w4 = idx & 7, kp = (idx >> 3) & 1023, bh = idx >> 13;
    const uint4* src = (const uint4*)(g_v + (size_t)bh * T_ * D_);
    uint4 a = src[(2 * kp)     * 8 + w4];
    uint4 b = src[(2 * kp + 1) * 8 + w4];
    uint32_t* dst = g_vp + ((size_t)bh * 1024 + kp) * 64 + w4 * 8;
    *(uint4*)dst = make_uint4(__byte_perm(a.x, b.x, 0x5410), __byte_perm(a.x, b.x, 0x7632),
                              __byte_perm(a.y, b.y, 0x5410), __byte_perm(a.y, b.y, 0x7632));
    *(uint4*)(dst + 4) = make_uint4(__byte_perm(a.z, b.z, 0x5410), __byte_perm(a.z, b.z, 0x7632),
                                    __byte_perm(a.w, b.w, 0x5410), __byte_perm(a.w, b.w, 0x7632));
}

// ---------------------------------------------------------------------------
// GEMM core: 3-stage cp.async pipeline. BM=128, BN=128, BK=32, 256 thr.
// 8 warps 4(m)x2(n); warp tile 32x64.
// ---------------------------------------------------------------------------
struct MMCtx {
    const __half* Ah;       // A rows, row stride DM_
    const uint32_t* Wp;     // k-pair packed weights
    int m0, n0, nk;
};

__device__ __forceinline__ void mm_core(const MMCtx& cx, float c[2][8][4],
                                        uint32_t (*As)[128][20],
                                        uint32_t (*Bs)[16][136]) {
    const int tid  = threadIdx.x;
    const int warp = tid >> 5, lane = tid & 31;
    const int g = lane >> 2, t = lane & 3;
    const int wm = warp >> 1, wn = warp & 1;

    auto load_stage = [&](int ki, int st) {
        int k0 = ki << 5;
        #pragma unroll
        for (int i = 0; i < 2; ++i) {
            int idx = tid + 256 * i;
            int r = idx >> 2, c4 = idx & 3;
            cpa16(&As[st][r][c4 * 4], cx.Ah + (size_t)(cx.m0 + r) * DM_ + k0 + c4 * 8);
        }
        #pragma unroll
        for (int i = 0; i < 2; ++i) {
            int idx = tid + 256 * i;
            int kp = idx >> 5, c4 = idx & 31;
            cpa16(&Bs[st][kp][c4 * 4],
                  cx.Wp + (size_t)((k0 >> 1) + kp) * INNER_ + cx.n0 + c4 * 4);
        }
        CP_COMMIT;
    };

    load_stage(0, 0);
    if (cx.nk > 1) load_stage(1, 1);
    for (int ki = 0; ki < cx.nk; ++ki) {
        int st = ki % 3;
        if (ki + 2 < cx.nk) { load_stage(ki + 2, (ki + 2) % 3); CP_WAIT2; }
        else if (ki + 1 < cx.nk) { CP_WAIT1; }
        else { CP_WAIT0; }
        __syncthreads();

        #pragma unroll
        for (int s = 0; s < 2; ++s) {
            uint32_t a[2][4];
            #pragma unroll
            for (int mf = 0; mf < 2; ++mf) {
                int rr = wm * 32 + mf * 16;
                a[mf][0] = As[st][rr + g    ][s * 8 + t    ];
                a[mf][1] = As[st][rr + g + 8][s * 8 + t    ];
                a[mf][2] = As[st][rr + g    ][s * 8 + t + 4];
                a[mf][3] = As[st][rr + g + 8][s * 8 + t + 4];
            }
            #pragma unroll
            for (int nf = 0; nf < 8; ++nf) {
                int cc = wn * 64 + nf * 8 + g;
                uint32_t b0 = Bs[st][s * 8 + t    ][cc];
                uint32_t b1 = Bs[st][s * 8 + t + 4][cc];
                mma16(c[0][nf][0], c[0][nf][1], c[0][nf][2], c[0][nf][3],
                      a[0][0], a[0][1], a[0][2], a[0][3], b0, b1);
                mma16(c[1][nf][0], c[1][nf][1], c[1][nf][2], c[1][nf][3],
                      a[1][0], a[1][1], a[1][2], a[1][3], b0, b1);
            }
        }
        __syncthreads();   // stage st reused by prefetch issued next iteration
    }
}

// ---------------------------------------------------------------------------
// Fused Q/K/V projection: grid (24, 64). which = blockIdx.x >> 3.
// Q epilogue folds the softmax scale into the stored fp16 values.
// ---------------------------------------------------------------------------
__global__ __launch_bounds__(256, 2) void mm_proj() {
    __shared__ uint32_t As[3][128][20];
    __shared__ uint32_t Bs[3][16][136];

    const int which = blockIdx.x >> 3;     // 0=Q, 1=K, 2=V
    MMCtx cx;
    cx.Ah = g_xh + ((which == 2) ? 0 : 512);
    cx.Wp = (which == 0) ? g_wq : (which == 1) ? g_wk : g_wv;
    cx.m0 = blockIdx.y * 128;
    cx.n0 = (blockIdx.x & 7) * 128;
    cx.nk = KPROJ >> 5;

    float c[2][8][4];
    #pragma unroll
    for (int mf = 0; mf < 2; ++mf)
        #pragma unroll
        for (int nf = 0; nf < 8; ++nf)
            #pragma unroll
            for (int e = 0; e < 4; ++e) c[mf][nf][e] = 0.f;

    mm_core(cx, c, As, Bs);

    const int tid = threadIdx.x, warp = tid >> 5, lane = tid & 31;
    const int g = lane >> 2, t = lane & 3;
    const int wm = warp >> 1, wn = warp & 1;
    __half* outp = (which == 0) ? g_q : (which == 1) ? g_k : g_v;
    const float sc = (which == 0) ? SCALE_LOG2E : 1.0f;

    #pragma unroll
    for (int mf = 0; mf < 2; ++mf) {
        #pragma unroll
        for (int nf = 0; nf < 8; ++nf) {
            int col = cx.n0 + wn * 64 + nf * 8 + 2 * t;
            int h = col >> 6, d = col & 63;
            int row = cx.m0 + wm * 32 + mf * 16 + g;
            int b = row >> 11, tt = row & (T_ - 1);
            *(uint32_t*)(outp + (((size_t)b * H_ + h) * T_ + tt) * D_ + d) =
                f22h2(c[mf][nf][0] * sc, c[mf][nf][1] * sc);
            row += 8; b = row >> 11; tt = row & (T_ - 1);
            *(uint32_t*)(outp + (((size_t)b * H_ + h) * T_ + tt) * D_ + d) =
                f22h2(c[mf][nf][2] * sc, c[mf][nf][3] * sc);
        }
    }
}

// ---------------------------------------------------------------------------
// Output GEMM: A = g_aoh, W = g_wo, fp32 out.
// ---------------------------------------------------------------------------
__global__ __launch_bounds__(256, 2) void mm_out(float* __restrict__ Cout) {
    __shared__ uint32_t As[3][128][20];
    __shared__ uint32_t Bs[3][16][136];

    MMCtx cx;
    cx.Ah = g_aoh;
    cx.Wp = g_wo;
    cx.m0 = blockIdx.y * 128;
    cx.n0 = blockIdx.x * 128;
    cx.nk = INNER_ >> 5;

    float c[2][8][4];
    #pragma unroll
    for (int mf = 0; mf < 2; ++mf)
        #pragma unroll
        for (int nf = 0; nf < 8; ++nf)
            #pragma unroll
            for (int e = 0; e < 4; ++e) c[mf][nf][e] = 0.f;

    mm_core(cx, c, As, Bs);

    const int tid = threadIdx.x, warp = tid >> 5, lane = tid & 31;
    const int g = lane >> 2, t = lane & 3;
    const int wm = warp >> 1, wn = warp & 1;

    #pragma unroll
    for (int mf = 0; mf < 2; ++mf) {
        #pragma unroll
        for (int nf = 0; nf < 8; ++nf) {
            int row = cx.m0 + wm * 32 + mf * 16 + g;
            int cc  = cx.n0 + wn * 64 + nf * 8 + 2 * t;
            *(float2*)(Cout + (size_t)row * DM_ + cc) =
                make_float2(c[mf][nf][0], c[mf][nf][1]);
            *(float2*)(Cout + (size_t)(row + 8) * DM_ + cc) =
                make_float2(c[mf][nf][2], c[mf][nf][3]);
        }
    }
}

// ---------------------------------------------------------------------------
// Flash attention, fp16 mma. 128 queries/block, 8 warps, warp tile 16x64.
// Q pre-scaled; cp.async double-buffered K/V.
// ---------------------------------------------------------------------------
#define ATTN_SMEM ((128*36 + 2*64*36 + 2*32*72) * 4)

__global__ __launch_bounds__(256, 2) void attn_f16() {
    extern __shared__ uint32_t smw[];
    uint32_t (*Qs)[36]     = (uint32_t(*)[36])smw;
    uint32_t (*Ks)[64][36] = (uint32_t(*)[64][36])(smw + 128 * 36);
    uint32_t (*Vs)[32][72] = (uint32_t(*)[32][72])(smw + 128 * 36 + 2 * 64 * 36);

    const int tid = threadIdx.x, warp = tid >> 5, lane = tid & 31;
    const int g = lane >> 2, t = lane & 3;
    const int bh = blockIdx.y;
    const int qb = (gridDim.x - 1) - blockIdx.x;   // heavy blocks first
    const int q0 = qb * 128;

    const uint4* Qg = (const uint4*)(g_q + ((size_t)bh * T_ + q0) * D_);
    #pragma unroll
    for (int i = 0; i < 4; ++i) {
        int idx = tid + 256 * i;
        int r = idx >> 3, w4 = idx & 7;
        *(uint4*)&Qs[r][w4 * 4] = Qg[idx];
    }

    auto load_kv = [&](int kt, int st) {
        const uint4* Kg = (const uint4*)(g_k + ((size_t)bh * T_ + kt * 64) * D_);
        #pragma unroll
        for (int i = 0; i < 2; ++i) {
            int idx = tid + 256 * i;
            int r = idx >> 3, w4 = idx & 7;
            cpa16(&Ks[st][r][w4 * 4], Kg + idx);
        }
        const uint4* Vg = (const uint4*)(g_vp + ((size_t)bh * (T_ / 2) + kt * 32) * D_);
        #pragma unroll
        for (int i = 0; i < 2; ++i) {
            int idx = tid + 256 * i;
            int kp = idx >> 4, u = idx & 15;
            cpa16(&Vs[st][kp][u * 4], Vg + idx);
        }
        CP_COMMIT;
    };

    float o[8][4];
    #pragma unroll
    for (int nf = 0; nf < 8; ++nf)
        #pragma unroll
        for (int e = 0; e < 4; ++e) o[nf][e] = 0.f;
    float mr[2] = {-1e30f, -1e30f}, lr[2] = {0.f, 0.f};

    const int rbase = q0 + warp * 16;
    const int nkt = 2 * qb + 2;

    load_kv(0, 0);
    for (int kt = 0; kt < nkt; ++kt) {
        int st = kt & 1;
        if (kt + 1 < nkt) { load_kv(kt + 1, st ^ 1); CP_WAIT1; }
        else              { CP_WAIT0; }
        __syncthreads();

        if (kt * 64 <= rbase + 15) {
            // --- S = Q @ K^T (16x64), log2-domain scores ---
            float sc[8][4];
            #pragma unroll
            for (int nf = 0; nf < 8; ++nf)
                #pragma unroll
                for (int e = 0; e < 4; ++e) sc[nf][e] = 0.f;
            #pragma unroll
            for (int s = 0; s < 4; ++s) {
                int rr = warp * 16;
                uint32_t a0 = Qs[rr + g    ][s * 8 + t    ];
                uint32_t a1 = Qs[rr + g + 8][s * 8 + t    ];
                uint32_t a2 = Qs[rr + g    ][s * 8 + t + 4];
                uint32_t a3 = Qs[rr + g + 8][s * 8 + t + 4];
                #pragma unroll
                for (int nf = 0; nf < 8; ++nf) {
                    uint32_t b0 = Ks[st][nf * 8 + g][s * 8 + t    ];
                    uint32_t b1 = Ks[st][nf * 8 + g][s * 8 + t + 4];
                    mma16(sc[nf][0], sc[nf][1], sc[nf][2], sc[nf][3],
                          a0, a1, a2, a3, b0, b1);
                }
            }

            // --- causal mask (boundary tiles) ---
            if (kt >= 2 * qb) {
                int row0 = rbase + g, row1 = row0 + 8;
                #pragma unroll
                for (int nf = 0; nf < 8; ++nf) {
                    int col = kt * 64 + nf * 8 + 2 * t;
                    if (col     > row0) sc[nf][0] = -1e30f;
                    if (col + 1 > row0) sc[nf][1] = -1e30f;
                    if (col     > row1) sc[nf][2] = -1e30f;
                    if (col + 1 > row1) sc[nf][3] = -1e30f;
                }
            }

            // --- online softmax (base-2) ---
            float mx[2] = {-1e30f, -1e30f};
            #pragma unroll
            for (int nf = 0; nf < 8; ++nf) {
                mx[0] = fmaxf(mx[0], fmaxf(sc[nf][0], sc[nf][1]));
                mx[1] = fmaxf(mx[1], fmaxf(sc[nf][2], sc[nf][3]));
            }
            #pragma unroll
            for (int rix = 0; rix < 2; ++rix) {
                mx[rix] = fmaxf(mx[rix], __shfl_xor_sync(0xffffffffu, mx[rix], 1));
                mx[rix] = fmaxf(mx[rix], __shfl_xor_sync(0xffffffffu, mx[rix], 2));
            }
            float mn[2], cor[2];
            #pragma unroll
            for (int rix = 0; rix < 2; ++rix) {
                mn[rix]  = fmaxf(mr[rix], mx[rix]);
                cor[rix] = ex2f(mr[rix] - mn[rix]);
                lr[rix] *= cor[rix];
                mr[rix]  = mn[rix];
            }
            #pragma unroll
            for (int nf = 0; nf < 8; ++nf) {
                o[nf][0] *= cor[0]; o[nf][1] *= cor[0];
                o[nf][2] *= cor[1]; o[nf][3] *= cor[1];
            }
            #pragma unroll
            for (int nf = 0; nf < 8; ++nf) {
                float p0 = ex2f(sc[nf][0] - mn[0]);
                float p1 = ex2f(sc[nf][1] - mn[0]);
                float p2 = ex2f(sc[nf][2] - mn[1]);
                float p3 = ex2f(sc[nf][3] - mn[1]);
                lr[0] += p0 + p1; lr[1] += p2 + p3;
                sc[nf][0] = p0; sc[nf][1] = p1;
                sc[nf][2] = p2; sc[nf][3] = p3;
            }

            // --- O += P @ V ---
            #pragma unroll
            for (int s = 0; s < 4; ++s) {
                uint32_t pa0 = f22h2(sc[2*s  ][0], sc[2*s  ][1]);
                uint32_t pa1 = f22h2(sc[2*s  ][2], sc[2*s  ][3]);
                uint32_t pa2 = f22h2(sc[2*s+1][0], sc[2*s+1][1]);
                uint32_t pa3 = f22h2(sc[2*s+1][2], sc[2*s+1][3]);
                #pragma unroll
                for (int nf = 0; nf < 8; ++nf) {
                    uint32_t b0 = Vs[st][s * 8 + t    ][nf * 8 + g];
                    uint32_t b1 = Vs[st][s * 8 + t + 4][nf * 8 + g];
                    mma16(o[nf][0], o[nf][1], o[nf][2], o[nf][3],
                          pa0, pa1, pa2, pa3, b0, b1);
                }
            }
        }
        __syncthreads();
    }

    // --- finalize ---
    #pragma unroll
    for (int rix = 0; rix < 2; ++rix) {
        lr[rix] += __shfl_xor_sync(0xffffffffu, lr[rix], 1);
        lr[rix] += __shfl_xor_sync(0xffffffffu, lr[rix], 2);
        lr[rix] = 1.f / lr[rix];
    }
    const int b = bh >> 4, h = bh & 15;
    uint32_t* d0 = (uint32_t*)(g_aoh + ((size_t)b * T_ + rbase + g    ) * INNER_ + h * 64);
    uint32_t* d1 = (uint32_t*)(g_aoh + ((size_t)b * T_ + rbase + g + 8) * INNER_ + h * 64);
    #pragma unroll
    for (int nf = 0; nf < 8; ++nf) {
        d0[nf * 4 + t] = f22h2(o[nf][0] * lr[0], o[nf][1] * lr[0]);
        d1[nf * 4 + t] = f22h2(o[nf][2] * lr[1], o[nf][3] * lr[1]);
    }
}

// ---------------------------------------------------------------------------
extern "C" void kernel_launch(void* const* d_in, const int* in_sizes, int n_in,
                              void* d_out, int out_size) {
    const float* x  = (const float*)d_in[0];
    const float* Wq = (const float*)d_in[1];
    const float* Wk = (const float*)d_in[2];
    const float* Wv = (const float*)d_in[3];
    const float* Wo = (const float*)d_in[4];
    float* out = (float*)d_out;

    cudaFuncSetAttribute(attn_f16, cudaFuncAttributeMaxDynamicSharedMemorySize,
                         ATTN_SMEM);

    prep_all<<<5376, 256>>>(x, Wq, Wk, Wv, Wo);
    mm_proj<<<dim3(24, 64), 256>>>();
    pack_v<<<(B_ * H_ * (T_ / 2) * 8) / 256, 256>>>();
    attn_f16<<<dim3(T_ / 128, B_ * H_), 256, ATTN_SMEM>>>();
    mm_out<<<dim3(8, 64), 256>>>(out);
}

// round 11
// speedup vs baseline: 1.4290x; 1.4290x over previous
#include <cuda_runtime.h>
#include <cuda_fp16.h>
#include <cstdint>

#define B_     4
#define T_     2048
#define H_     16
#define D_     64
#define INNER_ 1024
#define DM_    1024
#define KPROJ  512

// ---------------- device scratch (no allocation) ----------------
__device__ __half    g_xh [(size_t)B_*T_*DM_];          // x in fp16
__device__ uint32_t  g_wq [(KPROJ/2)*INNER_];           // weights, k-pair packed
__device__ uint32_t  g_wk [(KPROJ/2)*INNER_];
__device__ uint32_t  g_wv [(KPROJ/2)*INNER_];
__device__ uint32_t  g_wo [(INNER_/2)*DM_];
__device__ __half    g_q  [(size_t)B_*H_*T_*D_];        // pre-scaled by (1/8)*log2e
__device__ __half    g_k  [(size_t)B_*H_*T_*D_];
__device__ __half    g_v  [(size_t)B_*H_*T_*D_];
__device__ uint32_t  g_vp [(size_t)B_*H_*(T_/2)*D_];    // V key-pair packed
__device__ __half    g_aoh[(size_t)B_*T_*INNER_];       // attn out, [b][t][h*64+d]

#define SCALE_LOG2E 0.18033688011112042f   // (1/8) * log2(e)

// ---------------- helpers ----------------
__device__ __forceinline__ uint32_t f22h2(float lo, float hi) {
    __half2 h = __floats2half2_rn(lo, hi);
    return *reinterpret_cast<uint32_t*>(&h);
}
__device__ __forceinline__ float ex2f(float x) {
    float r; asm("ex2.approx.f32 %0, %1;" : "=f"(r) : "f"(x)); return r;
}
__device__ __forceinline__ void mma16(float& c0, float& c1, float& c2, float& c3,
                                      uint32_t a0, uint32_t a1, uint32_t a2, uint32_t a3,
                                      uint32_t b0, uint32_t b1) {
    asm volatile(
        "mma.sync.aligned.m16n8k16.row.col.f32.f16.f16.f32 "
        "{%0,%1,%2,%3},{%4,%5,%6,%7},{%8,%9},{%0,%1,%2,%3};"
        : "+f"(c0), "+f"(c1), "+f"(c2), "+f"(c3)
        : "r"(a0), "r"(a1), "r"(a2), "r"(a3), "r"(b0), "r"(b1));
}
__device__ __forceinline__ void cpa16(void* dst, const void* src) {
    uint32_t d = (uint32_t)__cvta_generic_to_shared(dst);
    asm volatile("cp.async.cg.shared.global [%0], [%1], 16;" :: "r"(d), "l"(src));
}
#define CP_COMMIT asm volatile("cp.async.commit_group;")
#define CP_WAIT1  asm volatile("cp.async.wait_group 1;")
#define CP_WAIT0  asm volatile("cp.async.wait_group 0;")

// ---------------- prep: x->fp16 + all 4 weights (one launch) ----------------
__device__ __forceinline__ void cvtw_body(const float* __restrict__ W,
                                          uint32_t* __restrict__ base, int lb) {
    int idx = lb * 256 + threadIdx.x;
    int kp = idx >> 8, c4 = idx & 255;
    float4 r0 = *(const float4*)(W + (size_t)(2 * kp)     * INNER_ + c4 * 4);
    float4 r1 = *(const float4*)(W + (size_t)(2 * kp + 1) * INNER_ + c4 * 4);
    *(uint4*)(base + (size_t)kp * INNER_ + c4 * 4) =
        make_uint4(f22h2(r0.x, r1.x), f22h2(r0.y, r1.y),
                   f22h2(r0.z, r1.z), f22h2(r0.w, r1.w));
}

__global__ __launch_bounds__(256) void prep_all(const float* __restrict__ x,
                                                const float* __restrict__ Wq,
                                                const float* __restrict__ Wk,
                                                const float* __restrict__ Wv,
                                                const float* __restrict__ Wo) {
    int blk = blockIdx.x;
    if (blk < 4096) {
        size_t i = ((size_t)blk * 256 + threadIdx.x) * 8;
        float4 a = *(const float4*)(x + i);
        float4 b = *(const float4*)(x + i + 4);
        *(uint4*)((uint32_t*)g_xh + i / 2) =
            make_uint4(f22h2(a.x, a.y), f22h2(a.z, a.w),
                       f22h2(b.x, b.y), f22h2(b.z, b.w));
    } else if (blk < 4352) cvtw_body(Wq, g_wq, blk - 4096);
    else if (blk < 4608)   cvtw_body(Wk, g_wk, blk - 4352);
    else if (blk < 4864)   cvtw_body(Wv, g_wv, blk - 4608);
    else                   cvtw_body(Wo, g_wo, blk - 4864);
}

// ---------------- prep: pack V into key-pair words ----------------
__global__ __launch_bounds__(256) void pack_v() {
    int idx = blockIdx.x * 256 + threadIdx.x;
    int w4 = idx & 7, kp = (idx >> 3) & 1023, bh = idx >> 13;
    const uint4* src = (const uint4*)(g_v + (size_t)bh * T_ * D_);
    uint4 a = src[(2 * kp)     * 8 + w4];
    uint4 b = src[(2 * kp + 1) * 8 + w4];
    uint32_t* dst = g_vp + ((size_t)bh * 1024 + kp) * 64 + w4 * 8;
    *(uint4*)dst = make_uint4(__byte_perm(a.x, b.x, 0x5410), __byte_perm(a.x, b.x, 0x7632),
                              __byte_perm(a.y, b.y, 0x5410), __byte_perm(a.y, b.y, 0x7632));
    *(uint4*)(dst + 4) = make_uint4(__byte_perm(a.z, b.z, 0x5410), __byte_perm(a.z, b.z, 0x7632),
                                    __byte_perm(a.w, b.w, 0x5410), __byte_perm(a.w, b.w, 0x7632));
}

// ---------------------------------------------------------------------------
// fp16 GEMM, 2-stage cp.async (round-8 proven). mode: 0=Q,1=K,2=V, 3=out GEMM.
// BM=128, BN=128, BK=32, 256 thr; 8 warps 4(m)x2(n); warp tile 32x64.
// Q-projection epilogue folds the softmax scale.
// ---------------------------------------------------------------------------
__global__ __launch_bounds__(256, 2) void mm_f16(float* __restrict__ Cout,
                                                 int mode, int Ktot) {
    __shared__ uint32_t As[2][128][20];
    __shared__ uint32_t Bs[2][16][136];

    const __half*   Ah = (mode == 3) ? g_aoh : (g_xh + ((mode == 2) ? 0 : 512));
    const uint32_t* Wp = (mode == 0) ? g_wq : (mode == 1) ? g_wk
                       : (mode == 2) ? g_wv : g_wo;

    const int tid  = threadIdx.x;
    const int warp = tid >> 5, lane = tid & 31;
    const int g = lane >> 2, t = lane & 3;
    const int wm = warp >> 1, wn = warp & 1;
    const int m0 = blockIdx.y * 128, n0 = blockIdx.x * 128;

    float c[2][8][4];
    #pragma unroll
    for (int mf = 0; mf < 2; ++mf)
        #pragma unroll
        for (int nf = 0; nf < 8; ++nf)
            #pragma unroll
            for (int e = 0; e < 4; ++e) c[mf][nf][e] = 0.f;

    auto load_stage = [&](int k0, int st) {
        #pragma unroll
        for (int i = 0; i < 2; ++i) {
            int idx = tid + 256 * i;
            int r = idx >> 2, c4 = idx & 3;
            cpa16(&As[st][r][c4 * 4], Ah + (size_t)(m0 + r) * DM_ + k0 + c4 * 8);
        }
        #pragma unroll
        for (int i = 0; i < 2; ++i) {
            int idx = tid + 256 * i;
            int kp = idx >> 5, c4 = idx & 31;
            cpa16(&Bs[st][kp][c4 * 4], Wp + (size_t)((k0 >> 1) + kp) * INNER_ + n0 + c4 * 4);
        }
        CP_COMMIT;
    };

    load_stage(0, 0);
    const int nk = Ktot >> 5;
    for (int ki = 0; ki < nk; ++ki) {
        int st = ki & 1;
        if (ki + 1 < nk) { load_stage((ki + 1) << 5, st ^ 1); CP_WAIT1; }
        else             { CP_WAIT0; }
        __syncthreads();

        #pragma unroll
        for (int s = 0; s < 2; ++s) {
            uint32_t a[2][4];
            #pragma unroll
            for (int mf = 0; mf < 2; ++mf) {
                int rr = wm * 32 + mf * 16;
                a[mf][0] = As[st][rr + g    ][s * 8 + t    ];
                a[mf][1] = As[st][rr + g + 8][s * 8 + t    ];
                a[mf][2] = As[st][rr + g    ][s * 8 + t + 4];
                a[mf][3] = As[st][rr + g + 8][s * 8 + t + 4];
            }
            #pragma unroll
            for (int nf = 0; nf < 8; ++nf) {
                int cc = wn * 64 + nf * 8 + g;
                uint32_t b0 = Bs[st][s * 8 + t    ][cc];
                uint32_t b1 = Bs[st][s * 8 + t + 4][cc];
                mma16(c[0][nf][0], c[0][nf][1], c[0][nf][2], c[0][nf][3],
                      a[0][0], a[0][1], a[0][2], a[0][3], b0, b1);
                mma16(c[1][nf][0], c[1][nf][1], c[1][nf][2], c[1][nf][3],
                      a[1][0], a[1][1], a[1][2], a[1][3], b0, b1);
            }
        }
        __syncthreads();
    }

    if (mode < 3) {
        __half* outp = (mode == 0) ? g_q : (mode == 1) ? g_k : g_v;
        const float sc = (mode == 0) ? SCALE_LOG2E : 1.0f;
        #pragma unroll
        for (int mf = 0; mf < 2; ++mf) {
            #pragma unroll
            for (int nf = 0; nf < 8; ++nf) {
                int col = n0 + wn * 64 + nf * 8 + 2 * t;
                int h = col >> 6, d = col & 63;
                int row = m0 + wm * 32 + mf * 16 + g;
                int b = row >> 11, tt = row & (T_ - 1);
                *(uint32_t*)(outp + (((size_t)b * H_ + h) * T_ + tt) * D_ + d) =
                    f22h2(c[mf][nf][0] * sc, c[mf][nf][1] * sc);
                row += 8; b = row >> 11; tt = row & (T_ - 1);
                *(uint32_t*)(outp + (((size_t)b * H_ + h) * T_ + tt) * D_ + d) =
                    f22h2(c[mf][nf][2] * sc, c[mf][nf][3] * sc);
            }
        }
    } else {
        #pragma unroll
        for (int mf = 0; mf < 2; ++mf) {
            #pragma unroll
            for (int nf = 0; nf < 8; ++nf) {
                int row = m0 + wm * 32 + mf * 16 + g;
                int cc  = n0 + wn * 64 + nf * 8 + 2 * t;
                *(float2*)(Cout + (size_t)row * DM_ + cc) =
                    make_float2(c[mf][nf][0], c[mf][nf][1]);
                *(float2*)(Cout + (size_t)(row + 8) * DM_ + cc) =
                    make_float2(c[mf][nf][2], c[mf][nf][3]);
            }
        }
    }
}

// ---------------------------------------------------------------------------
// Flash attention, fp16 mma. 128 queries/block, 4 warps, warp tile 32x64
// (round-7 proven shape) + cp.async double-buffered K/V + register P +
// pre-scaled Q + base-2 softmax.
// Dynamic smem: Qs[128][36] | Ks[2][64][36] | Vs[2][32][72] = 55296 B.
// ---------------------------------------------------------------------------
#define ATTN_SMEM ((128*36 + 2*64*36 + 2*32*72) * 4)

__global__ __launch_bounds__(128) void attn_f16() {
    extern __shared__ uint32_t smw[];
    uint32_t (*Qs)[36]     = (uint32_t(*)[36])smw;
    uint32_t (*Ks)[64][36] = (uint32_t(*)[64][36])(smw + 128 * 36);
    uint32_t (*Vs)[32][72] = (uint32_t(*)[32][72])(smw + 128 * 36 + 2 * 64 * 36);

    const int tid = threadIdx.x, warp = tid >> 5, lane = tid & 31;
    const int g = lane >> 2, t = lane & 3;
    const int bh = blockIdx.y;
    const int qb = (gridDim.x - 1) - blockIdx.x;   // heavy blocks first
    const int q0 = qb * 128;

    // --- stage Q (pre-scaled fp16) ---
    const uint4* Qg = (const uint4*)(g_q + ((size_t)bh * T_ + q0) * D_);
    #pragma unroll
    for (int i = 0; i < 8; ++i) {
        int idx = tid + 128 * i;
        int r = idx >> 3, w4 = idx & 7;
        *(uint4*)&Qs[r][w4 * 4] = Qg[idx];
    }

    auto load_kv = [&](int kt, int st) {
        const uint4* Kg = (const uint4*)(g_k + ((size_t)bh * T_ + kt * 64) * D_);
        #pragma unroll
        for (int i = 0; i < 4; ++i) {
            int idx = tid + 128 * i;
            int r = idx >> 3, w4 = idx & 7;
            cpa16(&Ks[st][r][w4 * 4], Kg + idx);
        }
        const uint4* Vg = (const uint4*)(g_vp + ((size_t)bh * (T_ / 2) + kt * 32) * D_);
        #pragma unroll
        for (int i = 0; i < 4; ++i) {
            int idx = tid + 128 * i;
            int kp = idx >> 4, u = idx & 15;
            cpa16(&Vs[st][kp][u * 4], Vg + idx);
        }
        CP_COMMIT;
    };

    float o[2][8][4];
    #pragma unroll
    for (int mf = 0; mf < 2; ++mf)
        #pragma unroll
        for (int nf = 0; nf < 8; ++nf)
            #pragma unroll
            for (int e = 0; e < 4; ++e) o[mf][nf][e] = 0.f;
    float mr[4] = {-1e30f, -1e30f, -1e30f, -1e30f};
    float lr[4] = {0.f, 0.f, 0.f, 0.f};

    const int rbase = q0 + warp * 32;
    const int nkt = 2 * qb + 2;

    load_kv(0, 0);
    for (int kt = 0; kt < nkt; ++kt) {
        int st = kt & 1;
        if (kt + 1 < nkt) { load_kv(kt + 1, st ^ 1); CP_WAIT1; }
        else              { CP_WAIT0; }
        __syncthreads();

        if (kt * 64 <= rbase + 31) {   // not fully masked for this warp
            // --- S = Q @ K^T (32x64 per warp), log2-domain ---
            float sc[2][8][4];
            #pragma unroll
            for (int mf = 0; mf < 2; ++mf)
                #pragma unroll
                for (int nf = 0; nf < 8; ++nf)
                    #pragma unroll
                    for (int e = 0; e < 4; ++e) sc[mf][nf][e] = 0.f;
            #pragma unroll
            for (int s = 0; s < 4; ++s) {
                uint32_t a[2][4];
                #pragma unroll
                for (int mf = 0; mf < 2; ++mf) {
                    int rr = warp * 32 + mf * 16;
                    a[mf][0] = Qs[rr + g    ][s * 8 + t    ];
                    a[mf][1] = Qs[rr + g + 8][s * 8 + t    ];
                    a[mf][2] = Qs[rr + g    ][s * 8 + t + 4];
                    a[mf][3] = Qs[rr + g + 8][s * 8 + t + 4];
                }
                #pragma unroll
                for (int nf = 0; nf < 8; ++nf) {
                    uint32_t b0 = Ks[st][nf * 8 + g][s * 8 + t    ];
                    uint32_t b1 = Ks[st][nf * 8 + g][s * 8 + t + 4];
                    mma16(sc[0][nf][0], sc[0][nf][1], sc[0][nf][2], sc[0][nf][3],
                          a[0][0], a[0][1], a[0][2], a[0][3], b0, b1);
                    mma16(sc[1][nf][0], sc[1][nf][1], sc[1][nf][2], sc[1][nf][3],
                          a[1][0], a[1][1], a[1][2], a[1][3], b0, b1);
                }
            }

            // --- causal mask (boundary tiles) ---
            if (kt >= 2 * qb) {
                #pragma unroll
                for (int mf = 0; mf < 2; ++mf) {
                    int row0 = rbase + mf * 16 + g;
                    int row1 = row0 + 8;
                    #pragma unroll
                    for (int nf = 0; nf < 8; ++nf) {
                        int col = kt * 64 + nf * 8 + 2 * t;
                        if (col     > row0) sc[mf][nf][0] = -1e30f;
                        if (col + 1 > row0) sc[mf][nf][1] = -1e30f;
                        if (col     > row1) sc[mf][nf][2] = -1e30f;
                        if (col + 1 > row1) sc[mf][nf][3] = -1e30f;
                    }
                }
            }

            // --- online softmax (base-2), 4 row-groups/thread ---
            float mx[4] = {-1e30f, -1e30f, -1e30f, -1e30f};
            #pragma unroll
            for (int mf = 0; mf < 2; ++mf)
                #pragma unroll
                for (int nf = 0; nf < 8; ++nf) {
                    mx[mf * 2 + 0] = fmaxf(mx[mf * 2 + 0], fmaxf(sc[mf][nf][0], sc[mf][nf][1]));
                    mx[mf * 2 + 1] = fmaxf(mx[mf * 2 + 1], fmaxf(sc[mf][nf][2], sc[mf][nf][3]));
                }
            #pragma unroll
            for (int rix = 0; rix < 4; ++rix) {
                mx[rix] = fmaxf(mx[rix], __shfl_xor_sync(0xffffffffu, mx[rix], 1));
                mx[rix] = fmaxf(mx[rix], __shfl_xor_sync(0xffffffffu, mx[rix], 2));
            }
            float mn[4], cor[4];
            #pragma unroll
            for (int rix = 0; rix < 4; ++rix) {
                mn[rix]  = fmaxf(mr[rix], mx[rix]);
                cor[rix] = ex2f(mr[rix] - mn[rix]);
                lr[rix] *= cor[rix];
                mr[rix]  = mn[rix];
            }
            #pragma unroll
            for (int mf = 0; mf < 2; ++mf)
                #pragma unroll
                for (int nf = 0; nf < 8; ++nf) {
                    o[mf][nf][0] *= cor[mf * 2 + 0]; o[mf][nf][1] *= cor[mf * 2 + 0];
                    o[mf][nf][2] *= cor[mf * 2 + 1]; o[mf][nf][3] *= cor[mf * 2 + 1];
                }
            #pragma unroll
            for (int mf = 0; mf < 2; ++mf)
                #pragma unroll
                for (int nf = 0; nf < 8; ++nf) {
                    float p0 = ex2f(sc[mf][nf][0] - mn[mf * 2 + 0]);
                    float p1 = ex2f(sc[mf][nf][1] - mn[mf * 2 + 0]);
                    float p2 = ex2f(sc[mf][nf][2] - mn[mf * 2 + 1]);
                    float p3 = ex2f(sc[mf][nf][3] - mn[mf * 2 + 1]);
                    lr[mf * 2 + 0] += p0 + p1;
                    lr[mf * 2 + 1] += p2 + p3;
                    sc[mf][nf][0] = p0; sc[mf][nf][1] = p1;
                    sc[mf][nf][2] = p2; sc[mf][nf][3] = p3;
                }

            // --- O += P @ V (P frags straight from registers) ---
            #pragma unroll
            for (int s = 0; s < 4; ++s) {
                uint32_t pa[2][4];
                #pragma unroll
                for (int mf = 0; mf < 2; ++mf) {
                    pa[mf][0] = f22h2(sc[mf][2*s  ][0], sc[mf][2*s  ][1]);
                    pa[mf][1] = f22h2(sc[mf][2*s  ][2], sc[mf][2*s  ][3]);
                    pa[mf][2] = f22h2(sc[mf][2*s+1][0], sc[mf][2*s+1][1]);
                    pa[mf][3] = f22h2(sc[mf][2*s+1][2], sc[mf][2*s+1][3]);
                }
                #pragma unroll
                for (int nf = 0; nf < 8; ++nf) {
                    uint32_t b0 = Vs[st][s * 8 + t    ][nf * 8 + g];
                    uint32_t b1 = Vs[st][s * 8 + t + 4][nf * 8 + g];
                    mma16(o[0][nf][0], o[0][nf][1], o[0][nf][2], o[0][nf][3],
                          pa[0][0], pa[0][1], pa[0][2], pa[0][3], b0, b1);
                    mma16(o[1][nf][0], o[1][nf][1], o[1][nf][2], o[1][nf][3],
                          pa[1][0], pa[1][1], pa[1][2], pa[1][3], b0, b1);
                }
            }
        }
        __syncthreads();   // stage st safe to overwrite next iteration
    }

    // --- finalize ---
    #pragma unroll
    for (int rix = 0; rix < 4; ++rix) {
        lr[rix] += __shfl_xor_sync(0xffffffffu, lr[rix], 1);
        lr[rix] += __shfl_xor_sync(0xffffffffu, lr[rix], 2);
        lr[rix] = 1.f / lr[rix];
    }
    const int b = bh >> 4, h = bh & 15;
    #pragma unroll
    for (int mf = 0; mf < 2; ++mf) {
        int r0 = rbase + mf * 16 + g;
        uint32_t* d0 = (uint32_t*)(g_aoh + ((size_t)b * T_ + r0    ) * INNER_ + h * 64);
        uint32_t* d1 = (uint32_t*)(g_aoh + ((size_t)b * T_ + r0 + 8) * INNER_ + h * 64);
        #pragma unroll
        for (int nf = 0; nf < 8; ++nf) {
            d0[nf * 4 + t] = f22h2(o[mf][nf][0] * lr[mf * 2 + 0],
                                   o[mf][nf][1] * lr[mf * 2 + 0]);
            d1[nf * 4 + t] = f22h2(o[mf][nf][2] * lr[mf * 2 + 1],
                                   o[mf][nf][3] * lr[mf * 2 + 1]);
        }
    }
}

// ---------------------------------------------------------------------------
extern "C" void kernel_launch(void* const* d_in, const int* in_sizes, int n_in,
                              void* d_out, int out_size) {
    const float* x  = (const float*)d_in[0];
    const float* Wq = (const float*)d_in[1];
    const float* Wk = (const float*)d_in[2];
    const float* Wv = (const float*)d_in[3];
    const float* Wo = (const float*)d_in[4];
    float* out = (float*)d_out;

    cudaFuncSetAttribute(attn_f16, cudaFuncAttributeMaxDynamicSharedMemorySize,
                         ATTN_SMEM);

    prep_all<<<5376, 256>>>(x, Wq, Wk, Wv, Wo);

    dim3 gg(INNER_ / 128, (B_ * T_) / 128);   // 8 x 64
    mm_f16<<<gg, 256>>>(nullptr, 0, KPROJ);
    mm_f16<<<gg, 256>>>(nullptr, 1, KPROJ);
    mm_f16<<<gg, 256>>>(nullptr, 2, KPROJ);
    pack_v<<<(B_ * H_ * (T_ / 2) * 8) / 256, 256>>>();
    attn_f16<<<dim3(T_ / 128, B_ * H_), 128, ATTN_SMEM>>>();
    mm_f16<<<gg, 256>>>(out, 3, INNER_);
}

// round 14
// speedup vs baseline: 1.4777x; 1.0341x over previous
#include <cuda_runtime.h>
#include <cuda_fp16.h>
#include <cstdint>

#define B_     4
#define T_     2048
#define H_     16
#define D_     64
#define INNER_ 1024
#define DM_    1024
#define KPROJ  512

// ---------------- device scratch (no allocation) ----------------
__device__ __half    g_xh [(size_t)B_*T_*DM_];        // x in fp16
__device__ __half    g_wtq[(size_t)INNER_*KPROJ];     // W^T fp16, [N][K] (n-major)
__device__ __half    g_wtk[(size_t)INNER_*KPROJ];
__device__ __half    g_wtv[(size_t)INNER_*KPROJ];
__device__ __half    g_wto[(size_t)DM_*INNER_];
__device__ __half    g_q  [(size_t)B_*H_*T_*D_];      // pre-scaled by (1/8)*log2e
__device__ __half    g_k  [(size_t)B_*H_*T_*D_];
__device__ __half    g_v  [(size_t)B_*H_*T_*D_];
__device__ uint32_t  g_vp [(size_t)B_*H_*(T_/2)*D_];  // V key-pair packed
__device__ __half    g_aoh[(size_t)B_*T_*INNER_];     // attn out, [b][t][h*64+d]

#define SCALE_LOG2E 0.18033688011112042f   // (1/8) * log2(e)

// ---------------- helpers ----------------
__device__ __forceinline__ uint32_t f22h2(float lo, float hi) {
    __half2 h = __floats2half2_rn(lo, hi);
    return *reinterpret_cast<uint32_t*>(&h);
}
__device__ __forceinline__ float ex2f(float x) {
    float r; asm("ex2.approx.f32 %0, %1;" : "=f"(r) : "f"(x)); return r;
}
__device__ __forceinline__ uint32_t smem_u32(const void* p) {
    return (uint32_t)__cvta_generic_to_shared(p);
}
__device__ __forceinline__ void mma16(float& c0, float& c1, float& c2, float& c3,
                                      uint32_t a0, uint32_t a1, uint32_t a2, uint32_t a3,
                                      uint32_t b0, uint32_t b1) {
    asm volatile(
        "mma.sync.aligned.m16n8k16.row.col.f32.f16.f16.f32 "
        "{%0,%1,%2,%3},{%4,%5,%6,%7},{%8,%9},{%0,%1,%2,%3};"
        : "+f"(c0), "+f"(c1), "+f"(c2), "+f"(c3)
        : "r"(a0), "r"(a1), "r"(a2), "r"(a3), "r"(b0), "r"(b1));
}
__device__ __forceinline__ void ldsm4(uint32_t& r0, uint32_t& r1,
                                      uint32_t& r2, uint32_t& r3, uint32_t addr) {
    asm volatile("ldmatrix.sync.aligned.m8n8.x4.shared.b16 {%0,%1,%2,%3}, [%4];"
                 : "=r"(r0), "=r"(r1), "=r"(r2), "=r"(r3) : "r"(addr));
}
__device__ __forceinline__ void ldsm2(uint32_t& r0, uint32_t& r1, uint32_t addr) {
    asm volatile("ldmatrix.sync.aligned.m8n8.x2.shared.b16 {%0,%1}, [%2];"
                 : "=r"(r0), "=r"(r1) : "r"(addr));
}
__device__ __forceinline__ void cpa16(void* dst, const void* src) {
    uint32_t d = smem_u32(dst);
    asm volatile("cp.async.cg.shared.global [%0], [%1], 16;" :: "r"(d), "l"(src));
}
#define CP_COMMIT asm volatile("cp.async.commit_group;")
#define CP_WAIT1  asm volatile("cp.async.wait_group 1;")
#define CP_WAIT0  asm volatile("cp.async.wait_group 0;")

// ---------------- prep: x->fp16 + W -> W^T fp16 [N][K] ----------------
__device__ __forceinline__ void trans_body(const float* __restrict__ W,
                                           __half* __restrict__ dst, int lb, int K) {
    int idx = lb * 256 + threadIdx.x;
    int nq = idx & 255, kq = idx >> 8;     // 4x4 block at (4kq, 4nq)
    float4 r0 = *(const float4*)(W + (size_t)(4 * kq + 0) * INNER_ + 4 * nq);
    float4 r1 = *(const float4*)(W + (size_t)(4 * kq + 1) * INNER_ + 4 * nq);
    float4 r2 = *(const float4*)(W + (size_t)(4 * kq + 2) * INNER_ + 4 * nq);
    float4 r3 = *(const float4*)(W + (size_t)(4 * kq + 3) * INNER_ + 4 * nq);
    const float* p0 = &r0.x; const float* p1 = &r1.x;
    const float* p2 = &r2.x; const float* p3 = &r3.x;
    #pragma unroll
    for (int j = 0; j < 4; ++j) {
        uint2 o = make_uint2(f22h2(p0[j], p1[j]), f22h2(p2[j], p3[j]));
        *(uint2*)(dst + (size_t)(4 * nq + j) * K + 4 * kq) = o;
    }
}

__global__ __launch_bounds__(256) void prep_all(const float* __restrict__ x,
                                                const float* __restrict__ Wq,
                                                const float* __restrict__ Wk,
                                                const float* __restrict__ Wv,
                                                const float* __restrict__ Wo) {
    int blk = blockIdx.x;
    if (blk < 4096) {
        size_t i = ((size_t)blk * 256 + threadIdx.x) * 8;
        float4 a = *(const float4*)(x + i);
        float4 b = *(const float4*)(x + i + 4);
        *(uint4*)((uint32_t*)g_xh + i / 2) =
            make_uint4(f22h2(a.x, a.y), f22h2(a.z, a.w),
                       f22h2(b.x, b.y), f22h2(b.z, b.w));
    } else if (blk < 4224) trans_body(Wq, g_wtq, blk - 4096, KPROJ);
    else if (blk < 4352)   trans_body(Wk, g_wtk, blk - 4224, KPROJ);
    else if (blk < 4480)   trans_body(Wv, g_wtv, blk - 4352, KPROJ);
    else                   trans_body(Wo, g_wto, blk - 4480, INNER_);
}

// ---------------- prep: pack V into key-pair words ----------------
__global__ __launch_bounds__(256) void pack_v() {
    int idx = blockIdx.x * 256 + threadIdx.x;
    int w4 = idx & 7, kp = (idx >> 3) & 1023, bh = idx >> 13;
    const uint4* src = (const uint4*)(g_v + (size_t)bh * T_ * D_);
    uint4 a = src[(2 * kp)     * 8 + w4];
    uint4 b = src[(2 * kp + 1) * 8 + w4];
    uint32_t* dst = g_vp + ((size_t)bh * 1024 + kp) * 64 + w4 * 8;
    *(uint4*)dst = make_uint4(__byte_perm(a.x, b.x, 0x5410), __byte_perm(a.x, b.x, 0x7632),
                              __byte_perm(a.y, b.y, 0x5410), __byte_perm(a.y, b.y, 0x7632));
    *(uint4*)(dst + 4) = make_uint4(__byte_perm(a.z, b.z, 0x5410), __byte_perm(a.z, b.z, 0x7632),
                                    __byte_perm(a.w, b.w, 0x5410), __byte_perm(a.w, b.w, 0x7632));
}

// ---------------------------------------------------------------------------
// fp16 GEMM, 2-stage cp.async + ldmatrix fragment loads.
// mode: 0=Q,1=K,2=V proj, 3=out GEMM. BM=128, BN=128, BK=32, 256 thr;
// 8 warps 4(m)x2(n); warp tile 32x64. A: [m][k-words]; B: [n][k-words] (n-major).
// Both padded to 20-word rows (80 B) -> ldmatrix row-start banks all distinct.
// ---------------------------------------------------------------------------
__global__ __launch_bounds__(256, 2) void mm_f16(float* __restrict__ Cout,
                                                 int mode, int Ktot) {
    __shared__ uint32_t As[2][128][20];
    __shared__ uint32_t Bs[2][128][20];

    const __half*    Ah = (mode == 3) ? g_aoh : (g_xh + ((mode == 2) ? 0 : 512));
    const uint32_t*  Wt = (const uint32_t*)((mode == 0) ? g_wtq : (mode == 1) ? g_wtk
                                          : (mode == 2) ? g_wtv : g_wto);
    const int Kw = Ktot >> 1;   // words per W^T row

    const int tid  = threadIdx.x;
    const int warp = tid >> 5, lane = tid & 31;
    const int g = lane >> 2, t = lane & 3;
    const int wm = warp >> 1, wn = warp & 1;
    const int m0 = blockIdx.y * 128, n0 = blockIdx.x * 128;

    // per-lane ldmatrix addresses (byte), stage-0 base; stage stride = 10240 B
    const uint32_t aB = smem_u32(&As[0][0][0]) +
        (((wm * 32 + (lane & 15)) * 20 + (lane >> 4) * 4) << 2);
    const uint32_t bB = smem_u32(&Bs[0][0][0]) +
        (((wn * 64 + (lane & 7)) * 20 + ((lane >> 3) & 1) * 4) << 2);

    float c[2][8][4];
    #pragma unroll
    for (int mf = 0; mf < 2; ++mf)
        #pragma unroll
        for (int nf = 0; nf < 8; ++nf)
            #pragma unroll
            for (int e = 0; e < 4; ++e) c[mf][nf][e] = 0.f;

    auto load_stage = [&](int k0, int st) {
        #pragma unroll
        for (int i = 0; i < 2; ++i) {
            int idx = tid + 256 * i;
            int r = idx >> 2, c4 = idx & 3;
            cpa16(&As[st][r][c4 * 4], Ah + (size_t)(m0 + r) * DM_ + k0 + c4 * 8);
        }
        #pragma unroll
        for (int i = 0; i < 2; ++i) {
            int idx = tid + 256 * i;
            int r = idx >> 2, c4 = idx & 3;
            cpa16(&Bs[st][r][c4 * 4], Wt + (size_t)(n0 + r) * Kw + (k0 >> 1) + c4 * 4);
        }
        CP_COMMIT;
    };

    load_stage(0, 0);
    const int nk = Ktot >> 5;
    for (int ki = 0; ki < nk; ++ki) {
        int st = ki & 1;
        if (ki + 1 < nk) { load_stage((ki + 1) << 5, st ^ 1); CP_WAIT1; }
        else             { CP_WAIT0; }
        __syncthreads();

        const uint32_t aS = aB + st * 10240;
        const uint32_t bS = bB + st * 10240;
        #pragma unroll
        for (int s = 0; s < 2; ++s) {
            uint32_t a[2][4];
            ldsm4(a[0][0], a[0][1], a[0][2], a[0][3], aS + s * 32);
            ldsm4(a[1][0], a[1][1], a[1][2], a[1][3], aS + 16 * 80 + s * 32);
            #pragma unroll
            for (int nf = 0; nf < 8; ++nf) {
                uint32_t b0, b1;
                ldsm2(b0, b1, bS + nf * 640 + s * 32);
                mma16(c[0][nf][0], c[0][nf][1], c[0][nf][2], c[0][nf][3],
                      a[0][0], a[0][1], a[0][2], a[0][3], b0, b1);
                mma16(c[1][nf][0], c[1][nf][1], c[1][nf][2], c[1][nf][3],
                      a[1][0], a[1][1], a[1][2], a[1][3], b0, b1);
            }
        }
        __syncthreads();
    }

    if (mode < 3) {
        __half* outp = (mode == 0) ? g_q : (mode == 1) ? g_k : g_v;
        const float sc = (mode == 0) ? SCALE_LOG2E : 1.0f;
        #pragma unroll
        for (int mf = 0; mf < 2; ++mf) {
            #pragma unroll
            for (int nf = 0; nf < 8; ++nf) {
                int col = n0 + wn * 64 + nf * 8 + 2 * t;
                int h = col >> 6, d = col & 63;
                int row = m0 + wm * 32 + mf * 16 + g;
                int b = row >> 11, tt = row & (T_ - 1);
                *(uint32_t*)(outp + (((size_t)b * H_ + h) * T_ + tt) * D_ + d) =
                    f22h2(c[mf][nf][0] * sc, c[mf][nf][1] * sc);
                row += 8; b = row >> 11; tt = row & (T_ - 1);
                *(uint32_t*)(outp + (((size_t)b * H_ + h) * T_ + tt) * D_ + d) =
                    f22h2(c[mf][nf][2] * sc, c[mf][nf][3] * sc);
            }
        }
    } else {
        #pragma unroll
        for (int mf = 0; mf < 2; ++mf) {
            #pragma unroll
            for (int nf = 0; nf < 8; ++nf) {
                int row = m0 + wm * 32 + mf * 16 + g;
                int cc  = n0 + wn * 64 + nf * 8 + 2 * t;
                *(float2*)(Cout + (size_t)row * DM_ + cc) =
                    make_float2(c[mf][nf][0], c[mf][nf][1]);
                *(float2*)(Cout + (size_t)(row + 8) * DM_ + cc) =
                    make_float2(c[mf][nf][2], c[mf][nf][3]);
            }
        }
    }
}

// ---------------------------------------------------------------------------
// Flash attention, fp16 mma. 128 thr, 4 warps, warp tile 32x64 (round-11
// structure) + hoisted Q fragments (ldmatrix.x4, once) + K via ldmatrix.x2.
// Dynamic smem: Qs[128][36] | Ks[2][64][36] | Vs[2][32][72] = 55296 B.
// ---------------------------------------------------------------------------
#define ATTN_SMEM ((128*36 + 2*64*36 + 2*32*72) * 4)

__global__ __launch_bounds__(128) void attn_f16() {
    extern __shared__ uint32_t smw[];
    uint32_t (*Qs)[36]     = (uint32_t(*)[36])smw;
    uint32_t (*Ks)[64][36] = (uint32_t(*)[64][36])(smw + 128 * 36);
    uint32_t (*Vs)[32][72] = (uint32_t(*)[32][72])(smw + 128 * 36 + 2 * 64 * 36);

    const int tid = threadIdx.x, warp = tid >> 5, lane = tid & 31;
    const int g = lane >> 2, t = lane & 3;
    const int bh = blockIdx.y;
    const int qb = (gridDim.x - 1) - blockIdx.x;   // heavy blocks first
    const int q0 = qb * 128;

    // --- stage Q (pre-scaled fp16) ---
    const uint4* Qg = (const uint4*)(g_q + ((size_t)bh * T_ + q0) * D_);
    #pragma unroll
    for (int i = 0; i < 8; ++i) {
        int idx = tid + 128 * i;
        int r = idx >> 3, w4 = idx & 7;
        *(uint4*)&Qs[r][w4 * 4] = Qg[idx];
    }

    auto load_kv = [&](int kt, int st) {
        const uint4* Kg = (const uint4*)(g_k + ((size_t)bh * T_ + kt * 64) * D_);
        #pragma unroll
        for (int i = 0; i < 4; ++i) {
            int idx = tid + 128 * i;
            int r = idx >> 3, w4 = idx & 7;
            cpa16(&Ks[st][r][w4 * 4], Kg + idx);
        }
        const uint4* Vg = (const uint4*)(g_vp + ((size_t)bh * (T_ / 2) + kt * 32) * D_);
        #pragma unroll
        for (int i = 0; i < 4; ++i) {
            int idx = tid + 128 * i;
            int kp = idx >> 4, u = idx & 15;
            cpa16(&Vs[st][kp][u * 4], Vg + idx);
        }
        CP_COMMIT;
    };

    load_kv(0, 0);
    __syncthreads();   // Q staged by all warps before fragment hoist

    // --- hoist Q fragments: qa[s][mf][0..3], via ldmatrix.x4 ---
    uint32_t qa[4][2][4];
    {
        const uint32_t qB = smem_u32(&Qs[0][0]) +
            (((warp * 32 + (lane & 15)) * 36 + (lane >> 4) * 4) << 2);
        #pragma unroll
        for (int s = 0; s < 4; ++s) {
            ldsm4(qa[s][0][0], qa[s][0][1], qa[s][0][2], qa[s][0][3],
                  qB + s * 32);
            ldsm4(qa[s][1][0], qa[s][1][1], qa[s][1][2], qa[s][1][3],
                  qB + 16 * 144 + s * 32);
        }
    }
    const uint32_t kB0 = smem_u32(&Ks[0][0][0]) +
        ((((lane & 7)) * 36 + ((lane >> 3) & 1) * 4) << 2);

    float o[2][8][4];
    #pragma unroll
    for (int mf = 0; mf < 2; ++mf)
        #pragma unroll
        for (int nf = 0; nf < 8; ++nf)
            #pragma unroll
            for (int e = 0; e < 4; ++e) o[mf][nf][e] = 0.f;
    float mr[4] = {-1e30f, -1e30f, -1e30f, -1e30f};
    float lr[4] = {0.f, 0.f, 0.f, 0.f};

    const int rbase = q0 + warp * 32;
    const int nkt = 2 * qb + 2;

    for (int kt = 0; kt < nkt; ++kt) {
        int st = kt & 1;
        if (kt + 1 < nkt) { load_kv(kt + 1, st ^ 1); CP_WAIT1; }
        else              { CP_WAIT0; }
        __syncthreads();

        if (kt * 64 <= rbase + 31) {
            // --- S = Q @ K^T (32x64 per warp), K frags via ldmatrix.x2 ---
            float sc[2][8][4];
            #pragma unroll
            for (int mf = 0; mf < 2; ++mf)
                #pragma unroll
                for (int nf = 0; nf < 8; ++nf)
                    #pragma unroll
                    for (int e = 0; e < 4; ++e) sc[mf][nf][e] = 0.f;
            const uint32_t kS = kB0 + st * 9216;   // 64*36*4
            #pragma unroll
            for (int s = 0; s < 4; ++s) {
                #pragma unroll
                for (int nf = 0; nf < 8; ++nf) {
                    uint32_t b0, b1;
                    ldsm2(b0, b1, kS + nf * 1152 + s * 32);
                    mma16(sc[0][nf][0], sc[0][nf][1], sc[0][nf][2], sc[0][nf][3],
                          qa[s][0][0], qa[s][0][1], qa[s][0][2], qa[s][0][3], b0, b1);
                    mma16(sc[1][nf][0], sc[1][nf][1], sc[1][nf][2], sc[1][nf][3],
                          qa[s][1][0], qa[s][1][1], qa[s][1][2], qa[s][1][3], b0, b1);
                }
            }

            // --- causal mask (boundary tiles) ---
            if (kt >= 2 * qb) {
                #pragma unroll
                for (int mf = 0; mf < 2; ++mf) {
                    int row0 = rbase + mf * 16 + g;
                    int row1 = row0 + 8;
                    #pragma unroll
                    for (int nf = 0; nf < 8; ++nf) {
                        int col = kt * 64 + nf * 8 + 2 * t;
                        if (col     > row0) sc[mf][nf][0] = -1e30f;
                        if (col + 1 > row0) sc[mf][nf][1] = -1e30f;
                        if (col     > row1) sc[mf][nf][2] = -1e30f;
                        if (col + 1 > row1) sc[mf][nf][3] = -1e30f;
                    }
                }
            }

            // --- online softmax (base-2), 4 row-groups/thread ---
            float mx[4] = {-1e30f, -1e30f, -1e30f, -1e30f};
            #pragma unroll
            for (int mf = 0; mf < 2; ++mf)
                #pragma unroll
                for (int nf = 0; nf < 8; ++nf) {
                    mx[mf * 2 + 0] = fmaxf(mx[mf * 2 + 0], fmaxf(sc[mf][nf][0], sc[mf][nf][1]));
                    mx[mf * 2 + 1] = fmaxf(mx[mf * 2 + 1], fmaxf(sc[mf][nf][2], sc[mf][nf][3]));
                }
            #pragma unroll
            for (int rix = 0; rix < 4; ++rix) {
                mx[rix] = fmaxf(mx[rix], __shfl_xor_sync(0xffffffffu, mx[rix], 1));
                mx[rix] = fmaxf(mx[rix], __shfl_xor_sync(0xffffffffu, mx[rix], 2));
            }
            float mn[4], cor[4];
            #pragma unroll
            for (int rix = 0; rix < 4; ++rix) {
                mn[rix]  = fmaxf(mr[rix], mx[rix]);
                cor[rix] = ex2f(mr[rix] - mn[rix]);
                lr[rix] *= cor[rix];
                mr[rix]  = mn[rix];
            }
            #pragma unroll
            for (int mf = 0; mf < 2; ++mf)
                #pragma unroll
                for (int nf = 0; nf < 8; ++nf) {
                    o[mf][nf][0] *= cor[mf * 2 + 0]; o[mf][nf][1] *= cor[mf * 2 + 0];
                    o[mf][nf][2] *= cor[mf * 2 + 1]; o[mf][nf][3] *= cor[mf * 2 + 1];
                }
            #pragma unroll
            for (int mf = 0; mf < 2; ++mf)
                #pragma unroll
                for (int nf = 0; nf < 8; ++nf) {
                    float p0 = ex2f(sc[mf][nf][0] - mn[mf * 2 + 0]);
                    float p1 = ex2f(sc[mf][nf][1] - mn[mf * 2 + 0]);
                    float p2 = ex2f(sc[mf][nf][2] - mn[mf * 2 + 1]);
                    float p3 = ex2f(sc[mf][nf][3] - mn[mf * 2 + 1]);
                    lr[mf * 2 + 0] += p0 + p1;
                    lr[mf * 2 + 1] += p2 + p3;
                    sc[mf][nf][0] = p0; sc[mf][nf][1] = p1;
                    sc[mf][nf][2] = p2; sc[mf][nf][3] = p3;
                }

            // --- O += P @ V (P frags straight from registers) ---
            #pragma unroll
            for (int s = 0; s < 4; ++s) {
                uint32_t pa[2][4];
                #pragma unroll
                for (int mf = 0; mf < 2; ++mf) {
                    pa[mf][0] = f22h2(sc[mf][2*s  ][0], sc[mf][2*s  ][1]);
                    pa[mf][1] = f22h2(sc[mf][2*s  ][2], sc[mf][2*s  ][3]);
                    pa[mf][2] = f22h2(sc[mf][2*s+1][0], sc[mf][2*s+1][1]);
                    pa[mf][3] = f22h2(sc[mf][2*s+1][2], sc[mf][2*s+1][3]);
                }
                #pragma unroll
                for (int nf = 0; nf < 8; ++nf) {
                    uint32_t b0 = Vs[st][s * 8 + t    ][nf * 8 + g];
                    uint32_t b1 = Vs[st][s * 8 + t + 4][nf * 8 + g];
                    mma16(o[0][nf][0], o[0][nf][1], o[0][nf][2], o[0][nf][3],
                          pa[0][0], pa[0][1], pa[0][2], pa[0][3], b0, b1);
                    mma16(o[1][nf][0], o[1][nf][1], o[1][nf][2], o[1][nf][3],
                          pa[1][0], pa[1][1], pa[1][2], pa[1][3], b0, b1);
                }
            }
        }
        __syncthreads();
    }

    // --- finalize ---
    #pragma unroll
    for (int rix = 0; rix < 4; ++rix) {
        lr[rix] += __shfl_xor_sync(0xffffffffu, lr[rix], 1);
        lr[rix] += __shfl_xor_sync(0xffffffffu, lr[rix], 2);
        lr[rix] = 1.f / lr[rix];
    }
    const int b = bh >> 4, h = bh & 15;
    #pragma unroll
    for (int mf = 0; mf < 2; ++mf) {
        int r0 = rbase + mf * 16 + g;
        uint32_t* d0 = (uint32_t*)(g_aoh + ((size_t)b * T_ + r0    ) * INNER_ + h * 64);
        uint32_t* d1 = (uint32_t*)(g_aoh + ((size_t)b * T_ + r0 + 8) * INNER_ + h * 64);
        #pragma unroll
        for (int nf = 0; nf < 8; ++nf) {
            d0[nf * 4 + t] = f22h2(o[mf][nf][0] * lr[mf * 2 + 0],
                                   o[mf][nf][1] * lr[mf * 2 + 0]);
            d1[nf * 4 + t] = f22h2(o[mf][nf][2] * lr[mf * 2 + 1],
                                   o[mf][nf][3] * lr[mf * 2 + 1]);
        }
    }
}

// ---------------------------------------------------------------------------
extern "C" void kernel_launch(void* const* d_in, const int* in_sizes, int n_in,
                              void* d_out, int out_size) {
    const float* x  = (const float*)d_in[0];
    const float* Wq = (const float*)d_in[1];
    const float* Wk = (const float*)d_in[2];
    const float* Wv = (const float*)d_in[3];
    const float* Wo = (const float*)d_in[4];
    float* out = (float*)d_out;

    cudaFuncSetAttribute(attn_f16, cudaFuncAttributeMaxDynamicSharedMemorySize,
                         ATTN_SMEM);

    prep_all<<<4736, 256>>>(x, Wq, Wk, Wv, Wo);

    dim3 gg(INNER_ / 128, (B_ * T_) / 128);   // 8 x 64
    mm_f16<<<gg, 256>>>(nullptr, 0, KPROJ);
    mm_f16<<<gg, 256>>>(nullptr, 1, KPROJ);
    mm_f16<<<gg, 256>>>(nullptr, 2, KPROJ);
    pack_v<<<(B_ * H_ * (T_ / 2) * 8) / 256, 256>>>();
    attn_f16<<<dim3(T_ / 128, B_ * H_), 128, ATTN_SMEM>>>();
    mm_f16<<<gg, 256>>>(out, 3, INNER_);
}